// round 4
// baseline (speedup 1.0000x reference)
#include <cuda_runtime.h>
#include <math.h>

// Problem constants
#define BATCH 2
#define S_LEN 2048
#define HID   1024
#define NH    16
#define HD    64
#define M_TOT (BATCH * S_LEN)       // 4096
#define BH    (BATCH * NH)          // 32

// Scratch (device globals: allocation-free)
__device__ float g_q[(size_t)BH * S_LEN * HD];   // [b*NH+h][s][d]
__device__ float g_k[(size_t)BH * S_LEN * HD];
__device__ float g_v[(size_t)BH * S_LEN * HD];
__device__ float g_ao[(size_t)M_TOT * HID];      // attention output [b*S+s][h*HD+d]
__device__ float g_cos[S_LEN * 32];              // RoPE tables [s][pair]
__device__ float g_sin[S_LEN * 32];

// ---------------------------------------------------------------------------
// RoPE table: double-precision sincos (immune to --use_fast_math, which
// turns fp32 sincosf into __sincosf with catastrophic range reduction at
// |x| ~ 2000 rad). Angle is formed exactly as the reference: fp32 inv_freq,
// fp32 s*inv, then precise trig of that fp32 value.
// ---------------------------------------------------------------------------
__global__ void rope_table_kernel()
{
    int idx = blockIdx.x * blockDim.x + threadIdx.x;   // 0 .. 65535
    int p = idx & 31;
    int s = idx >> 5;
    double invd = exp2(-13.287712379549449 * (double)(2 * p) / 64.0); // 10000^(-2p/64)
    float  invf = (float)invd;
    float  angf = (float)s * invf;       // fp32 rounding, matches reference freqs
    double sn, c;
    sincos((double)angf, &sn, &c);
    g_cos[idx] = (float)c;
    g_sin[idx] = (float)sn;
}

// ---------------------------------------------------------------------------
// NT GEMM: C[m,n] = sum_k A[m,k] * B[n,k]   (both row-major, K contiguous)
// BM=BN=128, BK=16, 256 threads, 8x8 per-thread tile.
// MODE 0: A = x, B = w_qkv, epilogue scatters to g_q/g_k/g_v head-major.
// MODE 1: A = g_ao,  B = w_o, epilogue writes plain row-major C.
// ---------------------------------------------------------------------------
template <int MODE>
__global__ void __launch_bounds__(256) gemm_nt_kernel(
    const float* __restrict__ A, const float* __restrict__ B,
    float* __restrict__ C, int M, int N, int K)
{
    const int BM = 128, BN = 128, BK = 16;
    __shared__ float As[BK][BM + 4];
    __shared__ float Bs[BK][BN + 4];

    const int tid = threadIdx.x;
    const int tx = tid & 15;        // 0..15 -> n micro
    const int ty = tid >> 4;        // 0..15 -> m micro
    const int bm = blockIdx.y * BM;
    const int bn = blockIdx.x * BN;

    const float* Aptr = (MODE == 0) ? A : g_ao;

    float acc[8][8];
#pragma unroll
    for (int i = 0; i < 8; i++)
#pragma unroll
        for (int j = 0; j < 8; j++) acc[i][j] = 0.0f;

    for (int k0 = 0; k0 < K; k0 += BK) {
        __syncthreads();
#pragma unroll
        for (int it = 0; it < 2; it++) {
            int idx = tid + it * 256;        // 0..511
            int row = idx >> 2;              // 0..127
            int c4  = idx & 3;               // 0..3 (float4 within 16 cols)
            float4 va = *(const float4*)(Aptr + (size_t)(bm + row) * K + k0 + c4 * 4);
            As[c4 * 4 + 0][row] = va.x;
            As[c4 * 4 + 1][row] = va.y;
            As[c4 * 4 + 2][row] = va.z;
            As[c4 * 4 + 3][row] = va.w;
            float4 vb = *(const float4*)(B + (size_t)(bn + row) * K + k0 + c4 * 4);
            Bs[c4 * 4 + 0][row] = vb.x;
            Bs[c4 * 4 + 1][row] = vb.y;
            Bs[c4 * 4 + 2][row] = vb.z;
            Bs[c4 * 4 + 3][row] = vb.w;
        }
        __syncthreads();

#pragma unroll
        for (int k = 0; k < BK; k++) {
            float a[8], b[8];
            float4 a0 = *(const float4*)&As[k][ty * 8];
            float4 a1 = *(const float4*)&As[k][ty * 8 + 4];
            float4 b0 = *(const float4*)&Bs[k][tx * 8];
            float4 b1 = *(const float4*)&Bs[k][tx * 8 + 4];
            a[0]=a0.x; a[1]=a0.y; a[2]=a0.z; a[3]=a0.w;
            a[4]=a1.x; a[5]=a1.y; a[6]=a1.z; a[7]=a1.w;
            b[0]=b0.x; b[1]=b0.y; b[2]=b0.z; b[3]=b0.w;
            b[4]=b1.x; b[5]=b1.y; b[6]=b1.z; b[7]=b1.w;
#pragma unroll
            for (int i = 0; i < 8; i++)
#pragma unroll
                for (int j = 0; j < 8; j++)
                    acc[i][j] = fmaf(a[i], b[j], acc[i][j]);
        }
    }

    if (MODE == 1) {
#pragma unroll
        for (int i = 0; i < 8; i++) {
            int m = bm + ty * 8 + i;
#pragma unroll
            for (int j = 0; j < 8; j++) {
                int n = bn + tx * 8 + j;
                C[(size_t)m * N + n] = acc[i][j];
            }
        }
    } else {
#pragma unroll
        for (int i = 0; i < 8; i++) {
            int m = bm + ty * 8 + i;
            int b = m >> 11;            // /2048
            int s = m & 2047;
#pragma unroll
            for (int j = 0; j < 8; j++) {
                int n   = bn + tx * 8 + j;
                int sec = n >> 10;      // 0=q 1=k 2=v
                int r   = n & 1023;
                int h   = r >> 6;
                int d   = r & 63;
                float* dst = (sec == 0) ? g_q : ((sec == 1) ? g_k : g_v);
                dst[(((size_t)(b * NH + h)) * S_LEN + s) * HD + d] = acc[i][j];
            }
        }
    }
}

// ---------------------------------------------------------------------------
// RoPE in-place on g_q and g_k via the precomputed table.
// ---------------------------------------------------------------------------
__global__ void rope_kernel()
{
    int idx = blockIdx.x * blockDim.x + threadIdx.x;
    int pair = idx & 31;  idx >>= 5;
    int s    = idx & 2047; idx >>= 11;
    int bh   = idx & 31;   idx >>= 5;   // idx now 0 (q) or 1 (k)
    float* ptr = (idx == 0 ? g_q : g_k) + ((size_t)bh * S_LEN + s) * HD;

    float c  = g_cos[s * 32 + pair];
    float sn = g_sin[s * 32 + pair];
    float x1 = ptr[pair];
    float x2 = ptr[pair + 32];
    ptr[pair]      = x1 * c - x2 * sn;
    ptr[pair + 32] = x2 * c + x1 * sn;
}

// ---------------------------------------------------------------------------
// Flash attention, fp32. BQ=BK=64, D=64. 256 threads = 16x16, 4x4 micro.
// grid = (S/BQ, BH). Causal: iterate kb=0..qb, mask only diagonal block.
// ---------------------------------------------------------------------------
#define LDT 68
#define ATTN_SMEM (4 * 64 * LDT * (int)sizeof(float))

__global__ void __launch_bounds__(256) attn_kernel()
{
    extern __shared__ float sm[];
    float* Qs = sm;                    // [d*LDT + q]
    float* Ks = Qs + 64 * LDT;         // [d*LDT + k]
    float* Vs = Ks + 64 * LDT;         // [k*LDT + d]
    float* Ps = Vs + 64 * LDT;         // [q*LDT + k]

    const int bh = blockIdx.y;
    const int qb = gridDim.x - 1 - blockIdx.x;   // heavy blocks first
    const int tid = threadIdx.x;
    const int tx = tid & 15;   // k / d columns
    const int ty = tid >> 4;   // q rows

    const float* Qg = g_q + ((size_t)bh * S_LEN + qb * 64) * HD;
    const float* Kg = g_k + (size_t)bh * S_LEN * HD;
    const float* Vg = g_v + (size_t)bh * S_LEN * HD;

    // Load Q tile transposed: Qs[d][q]
#pragma unroll
    for (int it = 0; it < 4; it++) {
        int idx = tid + it * 256;    // 0..1023
        int row = idx >> 4;          // q 0..63
        int c4  = idx & 15;          // float4 within 64 d
        float4 v = *(const float4*)(Qg + row * HD + c4 * 4);
        Qs[(c4 * 4 + 0) * LDT + row] = v.x;
        Qs[(c4 * 4 + 1) * LDT + row] = v.y;
        Qs[(c4 * 4 + 2) * LDT + row] = v.z;
        Qs[(c4 * 4 + 3) * LDT + row] = v.w;
    }

    float acc[4][4];
    float m_i[4], l_i[4];
#pragma unroll
    for (int i = 0; i < 4; i++) {
        m_i[i] = -1e30f; l_i[i] = 0.0f;
#pragma unroll
        for (int j = 0; j < 4; j++) acc[i][j] = 0.0f;
    }
    const float scale = 0.125f;   // 1/sqrt(64)

    for (int kb = 0; kb <= qb; kb++) {
        __syncthreads();   // previous PV done before overwriting K/V
#pragma unroll
        for (int it = 0; it < 4; it++) {
            int idx = tid + it * 256;
            int row = idx >> 4;
            int c4  = idx & 15;
            float4 vk = *(const float4*)(Kg + (size_t)(kb * 64 + row) * HD + c4 * 4);
            Ks[(c4 * 4 + 0) * LDT + row] = vk.x;
            Ks[(c4 * 4 + 1) * LDT + row] = vk.y;
            Ks[(c4 * 4 + 2) * LDT + row] = vk.z;
            Ks[(c4 * 4 + 3) * LDT + row] = vk.w;
            float4 vv = *(const float4*)(Vg + (size_t)(kb * 64 + row) * HD + c4 * 4);
            *(float4*)(Vs + row * LDT + c4 * 4) = vv;
        }
        __syncthreads();

        // S = Q K^T (4x4 per thread)
        float s4[4][4];
#pragma unroll
        for (int i = 0; i < 4; i++)
#pragma unroll
            for (int j = 0; j < 4; j++) s4[i][j] = 0.0f;

#pragma unroll 8
        for (int d = 0; d < 64; d++) {
            float4 fa = *(const float4*)(Qs + d * LDT + ty * 4);
            float4 fb = *(const float4*)(Ks + d * LDT + tx * 4);
            float a0=fa.x, a1=fa.y, a2=fa.z, a3=fa.w;
            float b0=fb.x, b1=fb.y, b2=fb.z, b3=fb.w;
            s4[0][0]=fmaf(a0,b0,s4[0][0]); s4[0][1]=fmaf(a0,b1,s4[0][1]); s4[0][2]=fmaf(a0,b2,s4[0][2]); s4[0][3]=fmaf(a0,b3,s4[0][3]);
            s4[1][0]=fmaf(a1,b0,s4[1][0]); s4[1][1]=fmaf(a1,b1,s4[1][1]); s4[1][2]=fmaf(a1,b2,s4[1][2]); s4[1][3]=fmaf(a1,b3,s4[1][3]);
            s4[2][0]=fmaf(a2,b0,s4[2][0]); s4[2][1]=fmaf(a2,b1,s4[2][1]); s4[2][2]=fmaf(a2,b2,s4[2][2]); s4[2][3]=fmaf(a2,b3,s4[2][3]);
            s4[3][0]=fmaf(a3,b0,s4[3][0]); s4[3][1]=fmaf(a3,b1,s4[3][1]); s4[3][2]=fmaf(a3,b2,s4[3][2]); s4[3][3]=fmaf(a3,b3,s4[3][3]);
        }

        const bool diag = (kb == qb);
#pragma unroll
        for (int i = 0; i < 4; i++) {
            int qg = qb * 64 + ty * 4 + i;
#pragma unroll
            for (int j = 0; j < 4; j++) {
                s4[i][j] *= scale;
                if (diag && (kb * 64 + tx * 4 + j > qg)) s4[i][j] = -1e30f;
            }
        }

        // Online softmax per q-row (reduce across the 16 tx lanes of half-warp)
#pragma unroll
        for (int i = 0; i < 4; i++) {
            float mx = fmaxf(fmaxf(s4[i][0], s4[i][1]), fmaxf(s4[i][2], s4[i][3]));
#pragma unroll
            for (int off = 1; off < 16; off <<= 1)
                mx = fmaxf(mx, __shfl_xor_sync(0xffffffffu, mx, off));
            float mnew = fmaxf(m_i[i], mx);
            float f = __expf(m_i[i] - mnew);
            m_i[i] = mnew;
            l_i[i] *= f;
#pragma unroll
            for (int j = 0; j < 4; j++) acc[i][j] *= f;
            float rs = 0.0f;
#pragma unroll
            for (int j = 0; j < 4; j++) {
                s4[i][j] = __expf(s4[i][j] - mnew);
                rs += s4[i][j];
            }
#pragma unroll
            for (int off = 1; off < 16; off <<= 1)
                rs += __shfl_xor_sync(0xffffffffu, rs, off);
            l_i[i] += rs;
            *(float4*)(Ps + (ty * 4 + i) * LDT + tx * 4) =
                make_float4(s4[i][0], s4[i][1], s4[i][2], s4[i][3]);
        }
        __syncthreads();

        // O += P V  (thread owns q rows ty*4+i, d cols tx*4+j)
#pragma unroll 8
        for (int kk = 0; kk < 64; kk++) {
            float4 fv = *(const float4*)(Vs + kk * LDT + tx * 4);
            float p0 = Ps[(ty * 4 + 0) * LDT + kk];
            float p1 = Ps[(ty * 4 + 1) * LDT + kk];
            float p2 = Ps[(ty * 4 + 2) * LDT + kk];
            float p3 = Ps[(ty * 4 + 3) * LDT + kk];
            acc[0][0]=fmaf(p0,fv.x,acc[0][0]); acc[0][1]=fmaf(p0,fv.y,acc[0][1]); acc[0][2]=fmaf(p0,fv.z,acc[0][2]); acc[0][3]=fmaf(p0,fv.w,acc[0][3]);
            acc[1][0]=fmaf(p1,fv.x,acc[1][0]); acc[1][1]=fmaf(p1,fv.y,acc[1][1]); acc[1][2]=fmaf(p1,fv.z,acc[1][2]); acc[1][3]=fmaf(p1,fv.w,acc[1][3]);
            acc[2][0]=fmaf(p2,fv.x,acc[2][0]); acc[2][1]=fmaf(p2,fv.y,acc[2][1]); acc[2][2]=fmaf(p2,fv.z,acc[2][2]); acc[2][3]=fmaf(p2,fv.w,acc[2][3]);
            acc[3][0]=fmaf(p3,fv.x,acc[3][0]); acc[3][1]=fmaf(p3,fv.y,acc[3][1]); acc[3][2]=fmaf(p3,fv.z,acc[3][2]); acc[3][3]=fmaf(p3,fv.w,acc[3][3]);
        }
    }

    // Write normalized output: g_ao[b*S+q][h*HD+d]
    const int b = bh >> 4, h = bh & 15;
#pragma unroll
    for (int i = 0; i < 4; i++) {
        int q = qb * 64 + ty * 4 + i;
        float inv = 1.0f / l_i[i];
#pragma unroll
        for (int j = 0; j < 4; j++) {
            int d = tx * 4 + j;
            g_ao[((size_t)(b * S_LEN + q)) * HID + h * HD + d] = acc[i][j] * inv;
        }
    }
}

// ---------------------------------------------------------------------------
extern "C" void kernel_launch(void* const* d_in, const int* in_sizes, int n_in,
                              void* d_out, int out_size)
{
    const float* x     = (const float*)d_in[0];
    const float* w_qkv = (const float*)d_in[1];
    const float* w_o   = (const float*)d_in[2];
    float* out = (float*)d_out;

    cudaFuncSetAttribute(attn_kernel,
                         cudaFuncAttributeMaxDynamicSharedMemorySize, ATTN_SMEM);

    // 0) RoPE cos/sin tables (double-precision trig, fast-math-proof)
    rope_table_kernel<<<(S_LEN * 32) / 256, 256>>>();

    // 1) QKV projection: [4096,1024] x [3072,1024]^T -> q/k/v head-major
    gemm_nt_kernel<0><<<dim3(3 * HID / 128, M_TOT / 128), 256>>>(
        x, w_qkv, nullptr, M_TOT, 3 * HID, HID);

    // 2) RoPE on q and k in place
    rope_kernel<<<(2 * BH * S_LEN * 32) / 256, 256>>>();

    // 3) Causal flash attention
    attn_kernel<<<dim3(S_LEN / 64, BH), 256, ATTN_SMEM>>>();

    // 4) Output projection -> d_out
    gemm_nt_kernel<1><<<dim3(HID / 128, M_TOT / 128), 256>>>(
        nullptr, w_o, out, M_TOT, HID, HID);
}

// round 13
// speedup vs baseline: 1.3877x; 1.3877x over previous
#include <cuda_runtime.h>
#include <cuda_bf16.h>
#include <math.h>
#include <stdint.h>

// Problem constants
#define BATCH 2
#define S_LEN 2048
#define HID   1024
#define NH    16
#define HD    64
#define M_TOT (BATCH * S_LEN)       // 4096
#define BH    (BATCH * NH)          // 32

// Scratch (device globals: allocation-free)
__device__ float g_q[(size_t)BH * S_LEN * HD];   // [b*NH+h][s][d]
__device__ float g_k[(size_t)BH * S_LEN * HD];
__device__ float g_v[(size_t)BH * S_LEN * HD];
__device__ float g_ao[(size_t)M_TOT * HID];      // attention output [b*S+s][h*HD+d]
__device__ float g_cos[S_LEN * 32];              // RoPE tables [s][pair]
__device__ float g_sin[S_LEN * 32];

// ===========================================================================
// RoPE table: double-precision sincos (immune to --use_fast_math; fp32
// __sincosf range reduction is catastrophically wrong at |x| ~ 2000 rad).
// ===========================================================================
__global__ void rope_table_kernel()
{
    int idx = blockIdx.x * blockDim.x + threadIdx.x;   // 0 .. 65535
    int p = idx & 31;
    int s = idx >> 5;
    double invd = exp2(-13.287712379549449 * (double)(2 * p) / 64.0); // 10000^(-2p/64)
    float  invf = (float)invd;
    float  angf = (float)s * invf;       // fp32 rounding, matches reference freqs
    double sn, c;
    sincos((double)angf, &sn, &c);
    g_cos[idx] = (float)c;
    g_sin[idx] = (float)sn;
}

// ===========================================================================
// HMMA GEMM via mma.sync (sm_80+ PTX, compiles on bare sm_103 target):
// C[m,n] = sum_k A[m,k]*B[n,k], fp32 via bf16 hi/lo 3-term split
// (Ah*Bh + Ah*Bl + Al*Bh; dropped Al*Bl ~ 2^-16 relative).
// CTA tile 128x128, BK=32, 256 threads = 8 warps (2 m x 4 n), warp 64x32.
// MODE 0: A=x, B=w_qkv -> scatter q/k/v head-major. MODE 1: A=g_ao, B=w_o -> C.
// ===========================================================================
#define BK 32
#define LDU 17   // row stride in u32 (16 u32 = 32 bf16, +1 pad)

__device__ __forceinline__ void cvt2(float a, float b, uint32_t& hi, uint32_t& lo)
{
    __nv_bfloat16 ah = __float2bfloat16_rn(a);
    __nv_bfloat16 bh = __float2bfloat16_rn(b);
    __nv_bfloat16 al = __float2bfloat16_rn(a - __bfloat162float(ah));
    __nv_bfloat16 bl = __float2bfloat16_rn(b - __bfloat162float(bh));
    __nv_bfloat162 hp = __halves2bfloat162(ah, bh);
    __nv_bfloat162 lp = __halves2bfloat162(al, bl);
    hi = *(uint32_t*)&hp;
    lo = *(uint32_t*)&lp;
}

#define MMA_BF16(c, a, b) \
    asm volatile("mma.sync.aligned.m16n8k16.row.col.f32.bf16.bf16.f32 " \
                 "{%0,%1,%2,%3}, {%4,%5,%6,%7}, {%8,%9}, {%0,%1,%2,%3};" \
                 : "+f"((c)[0]), "+f"((c)[1]), "+f"((c)[2]), "+f"((c)[3]) \
                 : "r"((a)[0]), "r"((a)[1]), "r"((a)[2]), "r"((a)[3]), \
                   "r"((b)[0]), "r"((b)[1]))

template <int MODE>
__global__ void __launch_bounds__(256) gemm_mma_kernel(
    const float* __restrict__ A, const float* __restrict__ B,
    float* __restrict__ C, int N, int K)
{
    __shared__ uint32_t As_hi[128 * LDU];
    __shared__ uint32_t As_lo[128 * LDU];
    __shared__ uint32_t Bs_hi[128 * LDU];
    __shared__ uint32_t Bs_lo[128 * LDU];

    const int tid  = threadIdx.x;
    const int wid  = tid >> 5;
    const int lane = tid & 31;
    const int g    = lane >> 2;       // groupID 0..7
    const int tig  = lane & 3;        // thread-in-group 0..3
    const int wm   = wid & 1;         // warp m 0..1 (64 rows each)
    const int wn   = wid >> 1;        // warp n 0..3 (32 cols each)
    const int bm   = blockIdx.y * 128;
    const int bn   = blockIdx.x * 128;
    const float* Aptr = (MODE == 0) ? A : g_ao;

    float acc[4][4][4];               // [mt][nt][frag]
#pragma unroll
    for (int i = 0; i < 4; i++)
#pragma unroll
        for (int j = 0; j < 4; j++)
#pragma unroll
            for (int f = 0; f < 4; f++) acc[i][j][f] = 0.0f;

    const int nchunks = K / BK;
    for (int c = 0; c < nchunks; c++) {
        const int k0 = c * BK;
        __syncthreads();
        // Load + convert: A,B tiles 128x32 fp32 -> bf16 hi/lo planes
#pragma unroll
        for (int it = 0; it < 4; it++) {
            int item = tid + it * 256;          // 0..1023
            int row  = item >> 3;               // 0..127
            int c4   = item & 7;                // float4 within 32 cols
            float4 va = *(const float4*)(Aptr + (size_t)(bm + row) * K + k0 + c4 * 4);
            uint32_t h0, l0, h1, l1;
            cvt2(va.x, va.y, h0, l0);
            cvt2(va.z, va.w, h1, l1);
            As_hi[row * LDU + c4 * 2]     = h0;
            As_hi[row * LDU + c4 * 2 + 1] = h1;
            As_lo[row * LDU + c4 * 2]     = l0;
            As_lo[row * LDU + c4 * 2 + 1] = l1;
            float4 vb = *(const float4*)(B + (size_t)(bn + row) * K + k0 + c4 * 4);
            cvt2(vb.x, vb.y, h0, l0);
            cvt2(vb.z, vb.w, h1, l1);
            Bs_hi[row * LDU + c4 * 2]     = h0;
            Bs_hi[row * LDU + c4 * 2 + 1] = h1;
            Bs_lo[row * LDU + c4 * 2]     = l0;
            Bs_lo[row * LDU + c4 * 2 + 1] = l1;
        }
        __syncthreads();

#pragma unroll
        for (int ks = 0; ks < 2; ks++) {        // two k16 steps per BK=32
            const int ko = ks * 8;              // u32 offset within row
            uint32_t ah[4][4], al[4][4], bh[4][2], bl[4][2];
#pragma unroll
            for (int mt = 0; mt < 4; mt++) {
                int r0 = (wm * 64 + mt * 16 + g) * LDU + ko;
                int r1 = r0 + 8 * LDU;
                ah[mt][0] = As_hi[r0 + tig];
                ah[mt][1] = As_hi[r1 + tig];
                ah[mt][2] = As_hi[r0 + tig + 4];
                ah[mt][3] = As_hi[r1 + tig + 4];
                al[mt][0] = As_lo[r0 + tig];
                al[mt][1] = As_lo[r1 + tig];
                al[mt][2] = As_lo[r0 + tig + 4];
                al[mt][3] = As_lo[r1 + tig + 4];
            }
#pragma unroll
            for (int nt = 0; nt < 4; nt++) {
                int rn = (wn * 32 + nt * 8 + g) * LDU + ko;
                bh[nt][0] = Bs_hi[rn + tig];
                bh[nt][1] = Bs_hi[rn + tig + 4];
                bl[nt][0] = Bs_lo[rn + tig];
                bl[nt][1] = Bs_lo[rn + tig + 4];
            }
#pragma unroll
            for (int mt = 0; mt < 4; mt++)
#pragma unroll
                for (int nt = 0; nt < 4; nt++) {
                    MMA_BF16(acc[mt][nt], ah[mt], bh[nt]);
                    MMA_BF16(acc[mt][nt], ah[mt], bl[nt]);
                    MMA_BF16(acc[mt][nt], al[mt], bh[nt]);
                }
        }
    }

    // Epilogue: fragment (mt,nt): rows wm*64+mt*16+{g, g+8}, cols wn*32+nt*8+tig*2+{0,1}
#pragma unroll
    for (int mt = 0; mt < 4; mt++) {
#pragma unroll
        for (int half = 0; half < 2; half++) {
            int m = bm + wm * 64 + mt * 16 + g + half * 8;
#pragma unroll
            for (int nt = 0; nt < 4; nt++) {
                float2 v = make_float2(acc[mt][nt][half * 2], acc[mt][nt][half * 2 + 1]);
                int n = bn + wn * 32 + nt * 8 + tig * 2;
                if (MODE == 1) {
                    *(float2*)(C + (size_t)m * N + n) = v;
                } else {
                    int b = m >> 11, s = m & 2047;
                    int sec = n >> 10;
                    int rr = n & 1023;
                    int h = rr >> 6, d = rr & 63;
                    float* dst = (sec == 0) ? g_q : ((sec == 1) ? g_k : g_v);
                    *(float2*)(dst + (((size_t)(b * NH + h)) * S_LEN + s) * HD + d) = v;
                }
            }
        }
    }
}

// ---------------------------------------------------------------------------
// RoPE in-place on g_q and g_k via the precomputed table.
// ---------------------------------------------------------------------------
__global__ void rope_kernel()
{
    int idx = blockIdx.x * blockDim.x + threadIdx.x;
    int pair = idx & 31;  idx >>= 5;
    int s    = idx & 2047; idx >>= 11;
    int bh   = idx & 31;   idx >>= 5;   // idx now 0 (q) or 1 (k)
    float* ptr = (idx == 0 ? g_q : g_k) + ((size_t)bh * S_LEN + s) * HD;

    float c  = g_cos[s * 32 + pair];
    float sn = g_sin[s * 32 + pair];
    float x1 = ptr[pair];
    float x2 = ptr[pair + 32];
    ptr[pair]      = x1 * c - x2 * sn;
    ptr[pair + 32] = x2 * c + x1 * sn;
}

// ---------------------------------------------------------------------------
// Flash attention, fp32. BQ=BK=64, D=64. 256 threads = 16x16, 4x4 micro.
// grid = (S/BQ, BH). Causal: iterate kb=0..qb, mask only diagonal block.
// ---------------------------------------------------------------------------
#define LDT 68
#define ATTN_SMEM (4 * 64 * LDT * (int)sizeof(float))

__global__ void __launch_bounds__(256) attn_kernel()
{
    extern __shared__ float sm[];
    float* Qs = sm;                    // [d*LDT + q]
    float* Ks = Qs + 64 * LDT;         // [d*LDT + k]
    float* Vs = Ks + 64 * LDT;         // [k*LDT + d]
    float* Ps = Vs + 64 * LDT;         // [q*LDT + k]

    const int bh = blockIdx.y;
    const int qb = gridDim.x - 1 - blockIdx.x;   // heavy blocks first
    const int tid = threadIdx.x;
    const int tx = tid & 15;   // k / d columns
    const int ty = tid >> 4;   // q rows

    const float* Qg = g_q + ((size_t)bh * S_LEN + qb * 64) * HD;
    const float* Kg = g_k + (size_t)bh * S_LEN * HD;
    const float* Vg = g_v + (size_t)bh * S_LEN * HD;

    // Load Q tile transposed: Qs[d][q]
#pragma unroll
    for (int it = 0; it < 4; it++) {
        int idx = tid + it * 256;    // 0..1023
        int row = idx >> 4;          // q 0..63
        int c4  = idx & 15;          // float4 within 64 d
        float4 v = *(const float4*)(Qg + row * HD + c4 * 4);
        Qs[(c4 * 4 + 0) * LDT + row] = v.x;
        Qs[(c4 * 4 + 1) * LDT + row] = v.y;
        Qs[(c4 * 4 + 2) * LDT + row] = v.z;
        Qs[(c4 * 4 + 3) * LDT + row] = v.w;
    }

    float acc[4][4];
    float m_i[4], l_i[4];
#pragma unroll
    for (int i = 0; i < 4; i++) {
        m_i[i] = -1e30f; l_i[i] = 0.0f;
#pragma unroll
        for (int j = 0; j < 4; j++) acc[i][j] = 0.0f;
    }
    const float scale = 0.125f;   // 1/sqrt(64)

    for (int kb = 0; kb <= qb; kb++) {
        __syncthreads();   // previous PV done before overwriting K/V
#pragma unroll
        for (int it = 0; it < 4; it++) {
            int idx = tid + it * 256;
            int row = idx >> 4;
            int c4  = idx & 15;
            float4 vk = *(const float4*)(Kg + (size_t)(kb * 64 + row) * HD + c4 * 4);
            Ks[(c4 * 4 + 0) * LDT + row] = vk.x;
            Ks[(c4 * 4 + 1) * LDT + row] = vk.y;
            Ks[(c4 * 4 + 2) * LDT + row] = vk.z;
            Ks[(c4 * 4 + 3) * LDT + row] = vk.w;
            float4 vv = *(const float4*)(Vg + (size_t)(kb * 64 + row) * HD + c4 * 4);
            *(float4*)(Vs + row * LDT + c4 * 4) = vv;
        }
        __syncthreads();

        // S = Q K^T (4x4 per thread)
        float s4[4][4];
#pragma unroll
        for (int i = 0; i < 4; i++)
#pragma unroll
            for (int j = 0; j < 4; j++) s4[i][j] = 0.0f;

#pragma unroll 8
        for (int d = 0; d < 64; d++) {
            float4 fa = *(const float4*)(Qs + d * LDT + ty * 4);
            float4 fb = *(const float4*)(Ks + d * LDT + tx * 4);
            float a0=fa.x, a1=fa.y, a2=fa.z, a3=fa.w;
            float b0=fb.x, b1=fb.y, b2=fb.z, b3=fb.w;
            s4[0][0]=fmaf(a0,b0,s4[0][0]); s4[0][1]=fmaf(a0,b1,s4[0][1]); s4[0][2]=fmaf(a0,b2,s4[0][2]); s4[0][3]=fmaf(a0,b3,s4[0][3]);
            s4[1][0]=fmaf(a1,b0,s4[1][0]); s4[1][1]=fmaf(a1,b1,s4[1][1]); s4[1][2]=fmaf(a1,b2,s4[1][2]); s4[1][3]=fmaf(a1,b3,s4[1][3]);
            s4[2][0]=fmaf(a2,b0,s4[2][0]); s4[2][1]=fmaf(a2,b1,s4[2][1]); s4[2][2]=fmaf(a2,b2,s4[2][2]); s4[2][3]=fmaf(a2,b3,s4[2][3]);
            s4[3][0]=fmaf(a3,b0,s4[3][0]); s4[3][1]=fmaf(a3,b1,s4[3][1]); s4[3][2]=fmaf(a3,b2,s4[3][2]); s4[3][3]=fmaf(a3,b3,s4[3][3]);
        }

        const bool diag = (kb == qb);
#pragma unroll
        for (int i = 0; i < 4; i++) {
            int qg = qb * 64 + ty * 4 + i;
#pragma unroll
            for (int j = 0; j < 4; j++) {
                s4[i][j] *= scale;
                if (diag && (kb * 64 + tx * 4 + j > qg)) s4[i][j] = -1e30f;
            }
        }

        // Online softmax per q-row (reduce across the 16 tx lanes of half-warp)
#pragma unroll
        for (int i = 0; i < 4; i++) {
            float mx = fmaxf(fmaxf(s4[i][0], s4[i][1]), fmaxf(s4[i][2], s4[i][3]));
#pragma unroll
            for (int off = 1; off < 16; off <<= 1)
                mx = fmaxf(mx, __shfl_xor_sync(0xffffffffu, mx, off));
            float mnew = fmaxf(m_i[i], mx);
            float f = __expf(m_i[i] - mnew);
            m_i[i] = mnew;
            l_i[i] *= f;
#pragma unroll
            for (int j = 0; j < 4; j++) acc[i][j] *= f;
            float rs = 0.0f;
#pragma unroll
            for (int j = 0; j < 4; j++) {
                s4[i][j] = __expf(s4[i][j] - mnew);
                rs += s4[i][j];
            }
#pragma unroll
            for (int off = 1; off < 16; off <<= 1)
                rs += __shfl_xor_sync(0xffffffffu, rs, off);
            l_i[i] += rs;
            *(float4*)(Ps + (ty * 4 + i) * LDT + tx * 4) =
                make_float4(s4[i][0], s4[i][1], s4[i][2], s4[i][3]);
        }
        __syncthreads();

        // O += P V  (thread owns q rows ty*4+i, d cols tx*4+j)
#pragma unroll 8
        for (int kk = 0; kk < 64; kk++) {
            float4 fv = *(const float4*)(Vs + kk * LDT + tx * 4);
            float p0 = Ps[(ty * 4 + 0) * LDT + kk];
            float p1 = Ps[(ty * 4 + 1) * LDT + kk];
            float p2 = Ps[(ty * 4 + 2) * LDT + kk];
            float p3 = Ps[(ty * 4 + 3) * LDT + kk];
            acc[0][0]=fmaf(p0,fv.x,acc[0][0]); acc[0][1]=fmaf(p0,fv.y,acc[0][1]); acc[0][2]=fmaf(p0,fv.z,acc[0][2]); acc[0][3]=fmaf(p0,fv.w,acc[0][3]);
            acc[1][0]=fmaf(p1,fv.x,acc[1][0]); acc[1][1]=fmaf(p1,fv.y,acc[1][1]); acc[1][2]=fmaf(p1,fv.z,acc[1][2]); acc[1][3]=fmaf(p1,fv.w,acc[1][3]);
            acc[2][0]=fmaf(p2,fv.x,acc[2][0]); acc[2][1]=fmaf(p2,fv.y,acc[2][1]); acc[2][2]=fmaf(p2,fv.z,acc[2][2]); acc[2][3]=fmaf(p2,fv.w,acc[2][3]);
            acc[3][0]=fmaf(p3,fv.x,acc[3][0]); acc[3][1]=fmaf(p3,fv.y,acc[3][1]); acc[3][2]=fmaf(p3,fv.z,acc[3][2]); acc[3][3]=fmaf(p3,fv.w,acc[3][3]);
        }
    }

    // Write normalized output: g_ao[b*S+q][h*HD+d]
    const int b = bh >> 4, h = bh & 15;
#pragma unroll
    for (int i = 0; i < 4; i++) {
        int q = qb * 64 + ty * 4 + i;
        float inv = 1.0f / l_i[i];
#pragma unroll
        for (int j = 0; j < 4; j++) {
            int d = tx * 4 + j;
            g_ao[((size_t)(b * S_LEN + q)) * HID + h * HD + d] = acc[i][j] * inv;
        }
    }
}

// ---------------------------------------------------------------------------
extern "C" void kernel_launch(void* const* d_in, const int* in_sizes, int n_in,
                              void* d_out, int out_size)
{
    const float* x     = (const float*)d_in[0];
    const float* w_qkv = (const float*)d_in[1];
    const float* w_o   = (const float*)d_in[2];
    float* out = (float*)d_out;

    cudaFuncSetAttribute(attn_kernel,
                         cudaFuncAttributeMaxDynamicSharedMemorySize, ATTN_SMEM);

    // 0) RoPE cos/sin tables (double-precision trig, fast-math-proof)
    rope_table_kernel<<<(S_LEN * 32) / 256, 256>>>();

    // 1) QKV projection (HMMA bf16 hi/lo): -> q/k/v head-major
    gemm_mma_kernel<0><<<dim3(3 * HID / 128, M_TOT / 128), 256>>>(
        x, w_qkv, nullptr, 3 * HID, HID);

    // 2) RoPE on q and k in place
    rope_kernel<<<(2 * BH * S_LEN * 32) / 256, 256>>>();

    // 3) Causal flash attention (fp32 SIMT)
    attn_kernel<<<dim3(S_LEN / 64, BH), 256, ATTN_SMEM>>>();

    // 4) Output projection (HMMA bf16 hi/lo) -> d_out
    gemm_mma_kernel<1><<<dim3(HID / 128, M_TOT / 128), 256>>>(
        nullptr, w_o, out, HID, HID);
}

// round 15
// speedup vs baseline: 2.1482x; 1.5480x over previous
#include <cuda_runtime.h>
#include <cuda_bf16.h>
#include <math.h>
#include <stdint.h>

// Problem constants
#define BATCH 2
#define S_LEN 2048
#define HID   1024
#define NH    16
#define HD    64
#define M_TOT (BATCH * S_LEN)       // 4096
#define BH    (BATCH * NH)          // 32

// Scratch (device globals: allocation-free)
__device__ float g_q[(size_t)BH * S_LEN * HD];   // [b*NH+h][s][d]
__device__ float g_k[(size_t)BH * S_LEN * HD];
__device__ float g_v[(size_t)BH * S_LEN * HD];
__device__ float g_ao[(size_t)M_TOT * HID];      // attention output [b*S+s][h*HD+d]
__device__ float g_cos[S_LEN * 32];              // RoPE tables [s][pair]
__device__ float g_sin[S_LEN * 32];

// ===========================================================================
// RoPE table: double-precision sincos (immune to --use_fast_math).
// ===========================================================================
__global__ void rope_table_kernel()
{
    int idx = blockIdx.x * blockDim.x + threadIdx.x;   // 0 .. 65535
    int p = idx & 31;
    int s = idx >> 5;
    double invd = exp2(-13.287712379549449 * (double)(2 * p) / 64.0); // 10000^(-2p/64)
    float  invf = (float)invd;
    float  angf = (float)s * invf;
    double sn, c;
    sincos((double)angf, &sn, &c);
    g_cos[idx] = (float)c;
    g_sin[idx] = (float)sn;
}

// ===========================================================================
// Shared helpers: bf16 hi/lo split + mma.sync (validated round 13)
// ===========================================================================
__device__ __forceinline__ void cvt2(float a, float b, uint32_t& hi, uint32_t& lo)
{
    __nv_bfloat16 ah = __float2bfloat16_rn(a);
    __nv_bfloat16 bh = __float2bfloat16_rn(b);
    __nv_bfloat16 al = __float2bfloat16_rn(a - __bfloat162float(ah));
    __nv_bfloat16 bl = __float2bfloat16_rn(b - __bfloat162float(bh));
    __nv_bfloat162 hp = __halves2bfloat162(ah, bh);
    __nv_bfloat162 lp = __halves2bfloat162(al, bl);
    hi = *(uint32_t*)&hp;
    lo = *(uint32_t*)&lp;
}

#define MMA_BF16(c, a, b) \
    asm volatile("mma.sync.aligned.m16n8k16.row.col.f32.bf16.bf16.f32 " \
                 "{%0,%1,%2,%3}, {%4,%5,%6,%7}, {%8,%9}, {%0,%1,%2,%3};" \
                 : "+f"((c)[0]), "+f"((c)[1]), "+f"((c)[2]), "+f"((c)[3]) \
                 : "r"((a)[0]), "r"((a)[1]), "r"((a)[2]), "r"((a)[3]), \
                   "r"((b)[0]), "r"((b)[1]))

// ===========================================================================
// HMMA GEMM (unchanged from round 13 WIN): fp32 via bf16 hi/lo 3-term split.
// CTA 128x128, BK=32, 256 threads = 8 warps (2m x 4n), warp 64x32.
// ===========================================================================
#define BK 32
#define LDU 17   // row stride in u32

template <int MODE>
__global__ void __launch_bounds__(256) gemm_mma_kernel(
    const float* __restrict__ A, const float* __restrict__ B,
    float* __restrict__ C, int N, int K)
{
    __shared__ uint32_t As_hi[128 * LDU];
    __shared__ uint32_t As_lo[128 * LDU];
    __shared__ uint32_t Bs_hi[128 * LDU];
    __shared__ uint32_t Bs_lo[128 * LDU];

    const int tid  = threadIdx.x;
    const int wid  = tid >> 5;
    const int lane = tid & 31;
    const int g    = lane >> 2;
    const int tig  = lane & 3;
    const int wm   = wid & 1;
    const int wn   = wid >> 1;
    const int bm   = blockIdx.y * 128;
    const int bn   = blockIdx.x * 128;
    const float* Aptr = (MODE == 0) ? A : g_ao;

    float acc[4][4][4];
#pragma unroll
    for (int i = 0; i < 4; i++)
#pragma unroll
        for (int j = 0; j < 4; j++)
#pragma unroll
            for (int f = 0; f < 4; f++) acc[i][j][f] = 0.0f;

    const int nchunks = K / BK;
    for (int c = 0; c < nchunks; c++) {
        const int k0 = c * BK;
        __syncthreads();
#pragma unroll
        for (int it = 0; it < 4; it++) {
            int item = tid + it * 256;
            int row  = item >> 3;
            int c4   = item & 7;
            float4 va = *(const float4*)(Aptr + (size_t)(bm + row) * K + k0 + c4 * 4);
            uint32_t h0, l0, h1, l1;
            cvt2(va.x, va.y, h0, l0);
            cvt2(va.z, va.w, h1, l1);
            As_hi[row * LDU + c4 * 2]     = h0;
            As_hi[row * LDU + c4 * 2 + 1] = h1;
            As_lo[row * LDU + c4 * 2]     = l0;
            As_lo[row * LDU + c4 * 2 + 1] = l1;
            float4 vb = *(const float4*)(B + (size_t)(bn + row) * K + k0 + c4 * 4);
            cvt2(vb.x, vb.y, h0, l0);
            cvt2(vb.z, vb.w, h1, l1);
            Bs_hi[row * LDU + c4 * 2]     = h0;
            Bs_hi[row * LDU + c4 * 2 + 1] = h1;
            Bs_lo[row * LDU + c4 * 2]     = l0;
            Bs_lo[row * LDU + c4 * 2 + 1] = l1;
        }
        __syncthreads();

#pragma unroll
        for (int ks = 0; ks < 2; ks++) {
            const int ko = ks * 8;
            uint32_t ah[4][4], al[4][4], bh[4][2], bl[4][2];
#pragma unroll
            for (int mt = 0; mt < 4; mt++) {
                int r0 = (wm * 64 + mt * 16 + g) * LDU + ko;
                int r1 = r0 + 8 * LDU;
                ah[mt][0] = As_hi[r0 + tig];
                ah[mt][1] = As_hi[r1 + tig];
                ah[mt][2] = As_hi[r0 + tig + 4];
                ah[mt][3] = As_hi[r1 + tig + 4];
                al[mt][0] = As_lo[r0 + tig];
                al[mt][1] = As_lo[r1 + tig];
                al[mt][2] = As_lo[r0 + tig + 4];
                al[mt][3] = As_lo[r1 + tig + 4];
            }
#pragma unroll
            for (int nt = 0; nt < 4; nt++) {
                int rn = (wn * 32 + nt * 8 + g) * LDU + ko;
                bh[nt][0] = Bs_hi[rn + tig];
                bh[nt][1] = Bs_hi[rn + tig + 4];
                bl[nt][0] = Bs_lo[rn + tig];
                bl[nt][1] = Bs_lo[rn + tig + 4];
            }
#pragma unroll
            for (int mt = 0; mt < 4; mt++)
#pragma unroll
                for (int nt = 0; nt < 4; nt++) {
                    MMA_BF16(acc[mt][nt], ah[mt], bh[nt]);
                    MMA_BF16(acc[mt][nt], ah[mt], bl[nt]);
                    MMA_BF16(acc[mt][nt], al[mt], bh[nt]);
                }
        }
    }

#pragma unroll
    for (int mt = 0; mt < 4; mt++) {
#pragma unroll
        for (int half = 0; half < 2; half++) {
            int m = bm + wm * 64 + mt * 16 + g + half * 8;
#pragma unroll
            for (int nt = 0; nt < 4; nt++) {
                float2 v = make_float2(acc[mt][nt][half * 2], acc[mt][nt][half * 2 + 1]);
                int n = bn + wn * 32 + nt * 8 + tig * 2;
                if (MODE == 1) {
                    *(float2*)(C + (size_t)m * N + n) = v;
                } else {
                    int b = m >> 11, s = m & 2047;
                    int sec = n >> 10;
                    int rr = n & 1023;
                    int h = rr >> 6, d = rr & 63;
                    float* dst = (sec == 0) ? g_q : ((sec == 1) ? g_k : g_v);
                    *(float2*)(dst + (((size_t)(b * NH + h)) * S_LEN + s) * HD + d) = v;
                }
            }
        }
    }
}

// ---------------------------------------------------------------------------
// RoPE in-place on g_q and g_k via the precomputed table.
// ---------------------------------------------------------------------------
__global__ void rope_kernel()
{
    int idx = blockIdx.x * blockDim.x + threadIdx.x;
    int pair = idx & 31;  idx >>= 5;
    int s    = idx & 2047; idx >>= 11;
    int bh   = idx & 31;   idx >>= 5;
    float* ptr = (idx == 0 ? g_q : g_k) + ((size_t)bh * S_LEN + s) * HD;

    float c  = g_cos[s * 32 + pair];
    float sn = g_sin[s * 32 + pair];
    float x1 = ptr[pair];
    float x2 = ptr[pair + 32];
    ptr[pair]      = x1 * c - x2 * sn;
    ptr[pair + 32] = x2 * c + x1 * sn;
}

// ===========================================================================
// HMMA flash attention. CTA = 64 q-rows, 128 threads (4 warps x 16 rows).
// QK^T: Q (pre-scaled) hi/lo x K hi/lo, 3 terms. P stays in registers:
// QK C-fragment layout == PV A-fragment layout (rows g/g+8, cols 2tig+{0,1}).
// PV: P hi/lo x V hi/lo, 3 terms. Online softmax on fragments, 4-lane shfl.
// Smem (u32): Qh/Ql [64][36], Kh/Kl [32][72] (pack over d), Vh/Vl [32][72]
// (pack over key pairs). Strides 36 (4 mod 32) / 72 (8 mod 32): fragment
// LDS bank = 4g+tig / 8tig+g — conflict-free.
// ===========================================================================
#define AQ_STRIDE 36
#define AK_STRIDE 72
#define ATTN_MMA_SMEM (6 * 2304 * (int)sizeof(uint32_t))   // 55296 B

__global__ void __launch_bounds__(128) attn_mma_kernel()
{
    extern __shared__ uint32_t smu[];
    uint32_t* Qh = smu;
    uint32_t* Ql = Qh + 2304;     // 64*36
    uint32_t* Kh = Ql + 2304;
    uint32_t* Kl = Kh + 2304;     // 32*72
    uint32_t* Vh = Kl + 2304;
    uint32_t* Vl = Vh + 2304;

    const int bh = blockIdx.y;
    const int qb = gridDim.x - 1 - blockIdx.x;   // heavy blocks first
    const int tid = threadIdx.x;
    const int wid = tid >> 5;
    const int lane = tid & 31;
    const int g = lane >> 2, tig = lane & 3;

    const float* Qg = g_q + ((size_t)bh * S_LEN + qb * 64) * HD;
    const float* Kg = g_k + (size_t)bh * S_LEN * HD;
    const float* Vg = g_v + (size_t)bh * S_LEN * HD;

    // Load Q tile (64x64), scale by 1/8, split hi/lo: Qh[q][d2]
    {
        int r = tid >> 1, half = tid & 1;
        const float* qr = Qg + r * HD;
#pragma unroll
        for (int j = 0; j < 8; j++) {
            int d = half * 32 + j * 4;
            float4 v = *(const float4*)(qr + d);
            v.x *= 0.125f; v.y *= 0.125f; v.z *= 0.125f; v.w *= 0.125f;
            uint32_t h0, l0, h1, l1;
            cvt2(v.x, v.y, h0, l0);
            cvt2(v.z, v.w, h1, l1);
            int o = r * AQ_STRIDE + d / 2;
            Qh[o] = h0; Ql[o] = l0;
            Qh[o + 1] = h1; Ql[o + 1] = l1;
        }
    }

    float o[8][4];
#pragma unroll
    for (int nb = 0; nb < 8; nb++)
#pragma unroll
        for (int f = 0; f < 4; f++) o[nb][f] = 0.0f;
    float m0 = -1e30f, m1 = -1e30f, l0s = 0.0f, l1s = 0.0f;

    for (int kb = 0; kb <= qb; kb++) {
        __syncthreads();   // previous iteration's MMA reads done
        // K tile: Kh[d2][key] = {K[key][2*d2], K[key][2*d2+1]}
        {
            int key = tid >> 1, half = tid & 1;
            const float* kr = Kg + (size_t)(kb * 64 + key) * HD;
#pragma unroll
            for (int j = 0; j < 8; j++) {
                int d = half * 32 + j * 4;
                float4 v = *(const float4*)(kr + d);
                uint32_t h0, l0, h1, l1;
                cvt2(v.x, v.y, h0, l0);
                cvt2(v.z, v.w, h1, l1);
                Kh[(d / 2) * AK_STRIDE + key] = h0;
                Kl[(d / 2) * AK_STRIDE + key] = l0;
                Kh[(d / 2 + 1) * AK_STRIDE + key] = h1;
                Kl[(d / 2 + 1) * AK_STRIDE + key] = l1;
            }
        }
        // V tile: Vh[k2][d] = {V[2*k2][d], V[2*k2+1][d]}
        {
            int k2 = tid >> 2, quarter = tid & 3;
            const float* v0p = Vg + (size_t)(kb * 64 + 2 * k2) * HD;
            const float* v1p = v0p + HD;
#pragma unroll
            for (int j = 0; j < 4; j++) {
                int d = quarter * 16 + j * 4;
                float4 a = *(const float4*)(v0p + d);
                float4 b = *(const float4*)(v1p + d);
                uint32_t h, l;
                int base = k2 * AK_STRIDE + d;
                cvt2(a.x, b.x, h, l); Vh[base] = h;     Vl[base] = l;
                cvt2(a.y, b.y, h, l); Vh[base + 1] = h; Vl[base + 1] = l;
                cvt2(a.z, b.z, h, l); Vh[base + 2] = h; Vl[base + 2] = l;
                cvt2(a.w, b.w, h, l); Vh[base + 3] = h; Vl[base + 3] = l;
            }
        }
        __syncthreads();

        // S = Q K^T (per warp: 16 q-rows x 64 keys), 3-term hi/lo
        float s[8][4];
#pragma unroll
        for (int nb = 0; nb < 8; nb++)
#pragma unroll
            for (int f = 0; f < 4; f++) s[nb][f] = 0.0f;

#pragma unroll
        for (int ks = 0; ks < 4; ks++) {
            uint32_t ah[4], al[4];
            int base = (wid * 16 + g) * AQ_STRIDE + ks * 8 + tig;
            ah[0] = Qh[base];
            ah[1] = Qh[base + 8 * AQ_STRIDE];
            ah[2] = Qh[base + 4];
            ah[3] = Qh[base + 8 * AQ_STRIDE + 4];
            al[0] = Ql[base];
            al[1] = Ql[base + 8 * AQ_STRIDE];
            al[2] = Ql[base + 4];
            al[3] = Ql[base + 8 * AQ_STRIDE + 4];
#pragma unroll
            for (int nb = 0; nb < 8; nb++) {
                uint32_t kh2[2], kl2[2];
                int kbase = (ks * 8 + tig) * AK_STRIDE + nb * 8 + g;
                kh2[0] = Kh[kbase];
                kh2[1] = Kh[kbase + 4 * AK_STRIDE];
                kl2[0] = Kl[kbase];
                kl2[1] = Kl[kbase + 4 * AK_STRIDE];
                MMA_BF16(s[nb], ah, kh2);
                MMA_BF16(s[nb], ah, kl2);
                MMA_BF16(s[nb], al, kh2);
            }
        }

        // Causal mask (diagonal block only)
        if (kb == qb) {
            int q0 = qb * 64 + wid * 16 + g;
            int q1 = q0 + 8;
#pragma unroll
            for (int nb = 0; nb < 8; nb++) {
                int k0 = kb * 64 + nb * 8 + tig * 2;
                if (k0 > q0)     s[nb][0] = -1e30f;
                if (k0 + 1 > q0) s[nb][1] = -1e30f;
                if (k0 > q1)     s[nb][2] = -1e30f;
                if (k0 + 1 > q1) s[nb][3] = -1e30f;
            }
        }

        // Online softmax: rows g (c0,c1) and g+8 (c2,c3); reduce over 4 lanes
        float mx0 = -1e30f, mx1 = -1e30f;
#pragma unroll
        for (int nb = 0; nb < 8; nb++) {
            mx0 = fmaxf(mx0, fmaxf(s[nb][0], s[nb][1]));
            mx1 = fmaxf(mx1, fmaxf(s[nb][2], s[nb][3]));
        }
#pragma unroll
        for (int off = 1; off < 4; off <<= 1) {
            mx0 = fmaxf(mx0, __shfl_xor_sync(0xffffffffu, mx0, off));
            mx1 = fmaxf(mx1, __shfl_xor_sync(0xffffffffu, mx1, off));
        }
        float mn0 = fmaxf(m0, mx0), mn1 = fmaxf(m1, mx1);
        float f0 = __expf(m0 - mn0), f1 = __expf(m1 - mn1);
        m0 = mn0; m1 = mn1;

        float rs0 = 0.0f, rs1 = 0.0f;
#pragma unroll
        for (int nb = 0; nb < 8; nb++) {
            s[nb][0] = __expf(s[nb][0] - mn0);
            s[nb][1] = __expf(s[nb][1] - mn0);
            s[nb][2] = __expf(s[nb][2] - mn1);
            s[nb][3] = __expf(s[nb][3] - mn1);
            rs0 += s[nb][0] + s[nb][1];
            rs1 += s[nb][2] + s[nb][3];
        }
#pragma unroll
        for (int off = 1; off < 4; off <<= 1) {
            rs0 += __shfl_xor_sync(0xffffffffu, rs0, off);
            rs1 += __shfl_xor_sync(0xffffffffu, rs1, off);
        }
        l0s = l0s * f0 + rs0;
        l1s = l1s * f1 + rs1;
#pragma unroll
        for (int nb = 0; nb < 8; nb++) {
            o[nb][0] *= f0; o[nb][1] *= f0;
            o[nb][2] *= f1; o[nb][3] *= f1;
        }

        // O += P V : P packed in-register (QK C-frag == PV A-frag layout)
#pragma unroll
        for (int ks = 0; ks < 4; ks++) {
            uint32_t pah[4], pal[4];
            cvt2(s[2 * ks][0],     s[2 * ks][1],     pah[0], pal[0]);
            cvt2(s[2 * ks][2],     s[2 * ks][3],     pah[1], pal[1]);
            cvt2(s[2 * ks + 1][0], s[2 * ks + 1][1], pah[2], pal[2]);
            cvt2(s[2 * ks + 1][2], s[2 * ks + 1][3], pah[3], pal[3]);
#pragma unroll
            for (int nb = 0; nb < 8; nb++) {
                uint32_t vh2[2], vl2[2];
                int vbase = (ks * 8 + tig) * AK_STRIDE + nb * 8 + g;
                vh2[0] = Vh[vbase];
                vh2[1] = Vh[vbase + 4 * AK_STRIDE];
                vl2[0] = Vl[vbase];
                vl2[1] = Vl[vbase + 4 * AK_STRIDE];
                MMA_BF16(o[nb], pah, vh2);
                MMA_BF16(o[nb], pah, vl2);
                MMA_BF16(o[nb], pal, vh2);
            }
        }
    }

    // Epilogue: normalize, write g_ao[b*S+q][h*64+d]
    const int b = bh >> 4, h = bh & 15;
    const float inv0 = 1.0f / l0s, inv1 = 1.0f / l1s;
    int q0 = qb * 64 + wid * 16 + g;
#pragma unroll
    for (int nb = 0; nb < 8; nb++) {
        int d = nb * 8 + tig * 2;
        float2 v0 = make_float2(o[nb][0] * inv0, o[nb][1] * inv0);
        *(float2*)(g_ao + ((size_t)(b * S_LEN + q0)) * HID + h * HD + d) = v0;
        float2 v1 = make_float2(o[nb][2] * inv1, o[nb][3] * inv1);
        *(float2*)(g_ao + ((size_t)(b * S_LEN + q0 + 8)) * HID + h * HD + d) = v1;
    }
}

// ---------------------------------------------------------------------------
extern "C" void kernel_launch(void* const* d_in, const int* in_sizes, int n_in,
                              void* d_out, int out_size)
{
    const float* x     = (const float*)d_in[0];
    const float* w_qkv = (const float*)d_in[1];
    const float* w_o   = (const float*)d_in[2];
    float* out = (float*)d_out;

    cudaFuncSetAttribute(attn_mma_kernel,
                         cudaFuncAttributeMaxDynamicSharedMemorySize, ATTN_MMA_SMEM);

    // 0) RoPE cos/sin tables (double-precision trig, fast-math-proof)
    rope_table_kernel<<<(S_LEN * 32) / 256, 256>>>();

    // 1) QKV projection (HMMA bf16 hi/lo): -> q/k/v head-major
    gemm_mma_kernel<0><<<dim3(3 * HID / 128, M_TOT / 128), 256>>>(
        x, w_qkv, nullptr, 3 * HID, HID);

    // 2) RoPE on q and k in place
    rope_kernel<<<(2 * BH * S_LEN * 32) / 256, 256>>>();

    // 3) Causal flash attention (HMMA bf16 hi/lo, P in registers)
    attn_mma_kernel<<<dim3(S_LEN / 64, BH), 128, ATTN_MMA_SMEM>>>();

    // 4) Output projection (HMMA bf16 hi/lo) -> d_out
    gemm_mma_kernel<1><<<dim3(HID / 128, M_TOT / 128), 256>>>(
        nullptr, w_o, out, HID, HID);
}

// round 16
// speedup vs baseline: 2.2930x; 1.0674x over previous
#include <cuda_runtime.h>
#include <cuda_bf16.h>
#include <math.h>
#include <stdint.h>

// Problem constants
#define BATCH 2
#define S_LEN 2048
#define HID   1024
#define NH    16
#define HD    64
#define M_TOT (BATCH * S_LEN)       // 4096
#define BH    (BATCH * NH)          // 32

// Scratch (device globals: allocation-free)
__device__ float g_q[(size_t)BH * S_LEN * HD];   // [b*NH+h][s][d]
__device__ float g_k[(size_t)BH * S_LEN * HD];
__device__ float g_v[(size_t)BH * S_LEN * HD];
__device__ float g_ao[(size_t)M_TOT * HID];      // attention output [b*S+s][h*HD+d]
__device__ float g_cos[S_LEN * 32];              // RoPE tables [s][pair]
__device__ float g_sin[S_LEN * 32];

// ===========================================================================
// RoPE table: double-precision sincos (immune to --use_fast_math).
// ===========================================================================
__global__ void rope_table_kernel()
{
    int idx = blockIdx.x * blockDim.x + threadIdx.x;   // 0 .. 65535
    int p = idx & 31;
    int s = idx >> 5;
    double invd = exp2(-13.287712379549449 * (double)(2 * p) / 64.0); // 10000^(-2p/64)
    float  invf = (float)invd;
    float  angf = (float)s * invf;
    double sn, c;
    sincos((double)angf, &sn, &c);
    g_cos[idx] = (float)c;
    g_sin[idx] = (float)sn;
}

// ===========================================================================
// Shared helpers: bf16 hi/lo split + mma.sync (validated rounds 13/15)
// ===========================================================================
__device__ __forceinline__ void cvt2(float a, float b, uint32_t& hi, uint32_t& lo)
{
    __nv_bfloat16 ah = __float2bfloat16_rn(a);
    __nv_bfloat16 bh = __float2bfloat16_rn(b);
    __nv_bfloat16 al = __float2bfloat16_rn(a - __bfloat162float(ah));
    __nv_bfloat16 bl = __float2bfloat16_rn(b - __bfloat162float(bh));
    __nv_bfloat162 hp = __halves2bfloat162(ah, bh);
    __nv_bfloat162 lp = __halves2bfloat162(al, bl);
    hi = *(uint32_t*)&hp;
    lo = *(uint32_t*)&lp;
}

#define MMA_BF16(c, a, b) \
    asm volatile("mma.sync.aligned.m16n8k16.row.col.f32.bf16.bf16.f32 " \
                 "{%0,%1,%2,%3}, {%4,%5,%6,%7}, {%8,%9}, {%0,%1,%2,%3};" \
                 : "+f"((c)[0]), "+f"((c)[1]), "+f"((c)[2]), "+f"((c)[3]) \
                 : "r"((a)[0]), "r"((a)[1]), "r"((a)[2]), "r"((a)[3]), \
                   "r"((b)[0]), "r"((b)[1]))

// ===========================================================================
// HMMA GEMM, double-buffered smem (one __syncthreads per K-chunk).
// fp32 via bf16 hi/lo 3-term split. CTA 128x128, BK=32, 256 thr, 8 warps.
// Buffer b at gsm + b*8704 u32: Ah 0, Al 2176, Bh 4352, Bl 6528.
// ===========================================================================
#define BK 32
#define LDU 17                       // row stride in u32
#define GBUF 8704                    // u32 per buffer (4 * 128*17)
#define GEMM_SMEM (2 * GBUF * (int)sizeof(uint32_t))   // 69632 B

template <int MODE>
__global__ void __launch_bounds__(256) gemm_mma_kernel(
    const float* __restrict__ A, const float* __restrict__ B,
    float* __restrict__ C, int N, int K)
{
    extern __shared__ uint32_t gsm[];

    const int tid  = threadIdx.x;
    const int wid  = tid >> 5;
    const int lane = tid & 31;
    const int g    = lane >> 2;
    const int tig  = lane & 3;
    const int wm   = wid & 1;
    const int wn   = wid >> 1;
    const int bm   = blockIdx.y * 128;
    const int bn   = blockIdx.x * 128;
    const float* Aptr = (MODE == 0) ? A : g_ao;

    float acc[4][4][4];
#pragma unroll
    for (int i = 0; i < 4; i++)
#pragma unroll
        for (int j = 0; j < 4; j++)
#pragma unroll
            for (int f = 0; f < 4; f++) acc[i][j][f] = 0.0f;

    const int nchunks = K / BK;
    for (int c = 0; c < nchunks; c++) {
        const int k0 = c * BK;
        uint32_t* buf = gsm + (c & 1) * GBUF;
        uint32_t* As_hi = buf;
        uint32_t* As_lo = buf + 2176;
        uint32_t* Bs_hi = buf + 4352;
        uint32_t* Bs_lo = buf + 6528;

        // Fill buffer c&1 (prev MMA on other buffer; write-after-read for this
        // buffer separated by the sync of the previous iteration).
#pragma unroll
        for (int it = 0; it < 4; it++) {
            int item = tid + it * 256;
            int row  = item >> 3;
            int c4   = item & 7;
            float4 va = *(const float4*)(Aptr + (size_t)(bm + row) * K + k0 + c4 * 4);
            uint32_t h0, l0, h1, l1;
            cvt2(va.x, va.y, h0, l0);
            cvt2(va.z, va.w, h1, l1);
            As_hi[row * LDU + c4 * 2]     = h0;
            As_hi[row * LDU + c4 * 2 + 1] = h1;
            As_lo[row * LDU + c4 * 2]     = l0;
            As_lo[row * LDU + c4 * 2 + 1] = l1;
            float4 vb = *(const float4*)(B + (size_t)(bn + row) * K + k0 + c4 * 4);
            cvt2(vb.x, vb.y, h0, l0);
            cvt2(vb.z, vb.w, h1, l1);
            Bs_hi[row * LDU + c4 * 2]     = h0;
            Bs_hi[row * LDU + c4 * 2 + 1] = h1;
            Bs_lo[row * LDU + c4 * 2]     = l0;
            Bs_lo[row * LDU + c4 * 2 + 1] = l1;
        }
        __syncthreads();

#pragma unroll
        for (int ks = 0; ks < 2; ks++) {
            const int ko = ks * 8;
            uint32_t ah[4][4], al[4][4], bh[4][2], bl[4][2];
#pragma unroll
            for (int mt = 0; mt < 4; mt++) {
                int r0 = (wm * 64 + mt * 16 + g) * LDU + ko;
                int r1 = r0 + 8 * LDU;
                ah[mt][0] = As_hi[r0 + tig];
                ah[mt][1] = As_hi[r1 + tig];
                ah[mt][2] = As_hi[r0 + tig + 4];
                ah[mt][3] = As_hi[r1 + tig + 4];
                al[mt][0] = As_lo[r0 + tig];
                al[mt][1] = As_lo[r1 + tig];
                al[mt][2] = As_lo[r0 + tig + 4];
                al[mt][3] = As_lo[r1 + tig + 4];
            }
#pragma unroll
            for (int nt = 0; nt < 4; nt++) {
                int rn = (wn * 32 + nt * 8 + g) * LDU + ko;
                bh[nt][0] = Bs_hi[rn + tig];
                bh[nt][1] = Bs_hi[rn + tig + 4];
                bl[nt][0] = Bs_lo[rn + tig];
                bl[nt][1] = Bs_lo[rn + tig + 4];
            }
#pragma unroll
            for (int mt = 0; mt < 4; mt++)
#pragma unroll
                for (int nt = 0; nt < 4; nt++) {
                    MMA_BF16(acc[mt][nt], ah[mt], bh[nt]);
                    MMA_BF16(acc[mt][nt], ah[mt], bl[nt]);
                    MMA_BF16(acc[mt][nt], al[mt], bh[nt]);
                }
        }
    }

#pragma unroll
    for (int mt = 0; mt < 4; mt++) {
#pragma unroll
        for (int half = 0; half < 2; half++) {
            int m = bm + wm * 64 + mt * 16 + g + half * 8;
#pragma unroll
            for (int nt = 0; nt < 4; nt++) {
                float2 v = make_float2(acc[mt][nt][half * 2], acc[mt][nt][half * 2 + 1]);
                int n = bn + wn * 32 + nt * 8 + tig * 2;
                if (MODE == 1) {
                    *(float2*)(C + (size_t)m * N + n) = v;
                } else {
                    int b = m >> 11, s = m & 2047;
                    int sec = n >> 10;
                    int rr = n & 1023;
                    int h = rr >> 6, d = rr & 63;
                    float* dst = (sec == 0) ? g_q : ((sec == 1) ? g_k : g_v);
                    *(float2*)(dst + (((size_t)(b * NH + h)) * S_LEN + s) * HD + d) = v;
                }
            }
        }
    }
}

// ---------------------------------------------------------------------------
// RoPE in-place on g_q and g_k via the precomputed table.
// ---------------------------------------------------------------------------
__global__ void rope_kernel()
{
    int idx = blockIdx.x * blockDim.x + threadIdx.x;
    int pair = idx & 31;  idx >>= 5;
    int s    = idx & 2047; idx >>= 11;
    int bh   = idx & 31;   idx >>= 5;
    float* ptr = (idx == 0 ? g_q : g_k) + ((size_t)bh * S_LEN + s) * HD;

    float c  = g_cos[s * 32 + pair];
    float sn = g_sin[s * 32 + pair];
    float x1 = ptr[pair];
    float x2 = ptr[pair + 32];
    ptr[pair]      = x1 * c - x2 * sn;
    ptr[pair + 32] = x2 * c + x1 * sn;
}

// ===========================================================================
// HMMA flash attention, BQ=128 q-rows per CTA, 256 threads (8 warps x 16 rows).
// K/V tiles 64 keys (convert cost amortized over 2x q-rows vs round 15).
// Fragment algebra identical to the validated round-15 kernel.
// Smem (u32): Qh/Ql [128][36], Kh/Kl [32][72], Vh/Vl [32][72]. Dynamic.
// ===========================================================================
#define AQ_STRIDE 36
#define AK_STRIDE 72
#define ATTN_MMA_SMEM ((2 * 128 * AQ_STRIDE + 4 * 32 * AK_STRIDE) * (int)sizeof(uint32_t)) // 73728 B

__global__ void __launch_bounds__(256) attn_mma_kernel()
{
    extern __shared__ uint32_t smu[];
    uint32_t* Qh = smu;                    // 128*36 = 4608
    uint32_t* Ql = Qh + 4608;
    uint32_t* Kh = Ql + 4608;              // 32*72 = 2304
    uint32_t* Kl = Kh + 2304;
    uint32_t* Vh = Kl + 2304;
    uint32_t* Vl = Vh + 2304;

    const int bh = blockIdx.y;
    const int qb = gridDim.x - 1 - blockIdx.x;   // heavy blocks first
    const int tid = threadIdx.x;
    const int wid = tid >> 5;                    // 0..7
    const int lane = tid & 31;
    const int g = lane >> 2, tig = lane & 3;

    const float* Qg = g_q + ((size_t)bh * S_LEN + qb * 128) * HD;
    const float* Kg = g_k + (size_t)bh * S_LEN * HD;
    const float* Vg = g_v + (size_t)bh * S_LEN * HD;

    // Load Q tile (128x64), scale by 1/8, split hi/lo: Qh[q][d2]
    {
        int r = tid >> 1, half = tid & 1;
        const float* qr = Qg + r * HD;
#pragma unroll
        for (int j = 0; j < 8; j++) {
            int d = half * 32 + j * 4;
            float4 v = *(const float4*)(qr + d);
            v.x *= 0.125f; v.y *= 0.125f; v.z *= 0.125f; v.w *= 0.125f;
            uint32_t h0, l0, h1, l1;
            cvt2(v.x, v.y, h0, l0);
            cvt2(v.z, v.w, h1, l1);
            int o = r * AQ_STRIDE + d / 2;
            Qh[o] = h0; Ql[o] = l0;
            Qh[o + 1] = h1; Ql[o + 1] = l1;
        }
    }

    float o[8][4];
#pragma unroll
    for (int nb = 0; nb < 8; nb++)
#pragma unroll
        for (int f = 0; f < 4; f++) o[nb][f] = 0.0f;
    float m0 = -1e30f, m1 = -1e30f, l0s = 0.0f, l1s = 0.0f;

    const int nkb = 2 * qb + 2;     // K-tiles of 64 covering keys < (qb+1)*128
    for (int kb = 0; kb < nkb; kb++) {
        __syncthreads();   // previous iteration's MMA reads done
        // K tile: Kh[d2][key] (64 keys; 4 threads per key)
        {
            int key = tid >> 2, quarter = tid & 3;
            const float* kr = Kg + (size_t)(kb * 64 + key) * HD;
#pragma unroll
            for (int j = 0; j < 4; j++) {
                int d = quarter * 16 + j * 4;
                float4 v = *(const float4*)(kr + d);
                uint32_t h0, l0, h1, l1;
                cvt2(v.x, v.y, h0, l0);
                cvt2(v.z, v.w, h1, l1);
                Kh[(d / 2) * AK_STRIDE + key] = h0;
                Kl[(d / 2) * AK_STRIDE + key] = l0;
                Kh[(d / 2 + 1) * AK_STRIDE + key] = h1;
                Kl[(d / 2 + 1) * AK_STRIDE + key] = l1;
            }
        }
        // V tile: Vh[k2][d] = {V[2*k2][d], V[2*k2+1][d]} (8 threads per pair)
        {
            int k2 = tid >> 3, e = tid & 7;
            const float* v0p = Vg + (size_t)(kb * 64 + 2 * k2) * HD;
            const float* v1p = v0p + HD;
#pragma unroll
            for (int j = 0; j < 2; j++) {
                int d = e * 8 + j * 4;
                float4 a = *(const float4*)(v0p + d);
                float4 b = *(const float4*)(v1p + d);
                uint32_t h, l;
                int base = k2 * AK_STRIDE + d;
                cvt2(a.x, b.x, h, l); Vh[base] = h;     Vl[base] = l;
                cvt2(a.y, b.y, h, l); Vh[base + 1] = h; Vl[base + 1] = l;
                cvt2(a.z, b.z, h, l); Vh[base + 2] = h; Vl[base + 2] = l;
                cvt2(a.w, b.w, h, l); Vh[base + 3] = h; Vl[base + 3] = l;
            }
        }
        __syncthreads();

        // S = Q K^T (per warp: 16 q-rows x 64 keys), 3-term hi/lo
        float s[8][4];
#pragma unroll
        for (int nb = 0; nb < 8; nb++)
#pragma unroll
            for (int f = 0; f < 4; f++) s[nb][f] = 0.0f;

#pragma unroll
        for (int ks = 0; ks < 4; ks++) {
            uint32_t ah[4], al[4];
            int base = (wid * 16 + g) * AQ_STRIDE + ks * 8 + tig;
            ah[0] = Qh[base];
            ah[1] = Qh[base + 8 * AQ_STRIDE];
            ah[2] = Qh[base + 4];
            ah[3] = Qh[base + 8 * AQ_STRIDE + 4];
            al[0] = Ql[base];
            al[1] = Ql[base + 8 * AQ_STRIDE];
            al[2] = Ql[base + 4];
            al[3] = Ql[base + 8 * AQ_STRIDE + 4];
#pragma unroll
            for (int nb = 0; nb < 8; nb++) {
                uint32_t kh2[2], kl2[2];
                int kbase = (ks * 8 + tig) * AK_STRIDE + nb * 8 + g;
                kh2[0] = Kh[kbase];
                kh2[1] = Kh[kbase + 4 * AK_STRIDE];
                kl2[0] = Kl[kbase];
                kl2[1] = Kl[kbase + 4 * AK_STRIDE];
                MMA_BF16(s[nb], ah, kh2);
                MMA_BF16(s[nb], ah, kl2);
                MMA_BF16(s[nb], al, kh2);
            }
        }

        // Causal mask (only the last two K-tiles can intersect the diagonal)
        if (kb >= 2 * qb) {
            int q0 = qb * 128 + wid * 16 + g;
            int q1 = q0 + 8;
#pragma unroll
            for (int nb = 0; nb < 8; nb++) {
                int k0 = kb * 64 + nb * 8 + tig * 2;
                if (k0 > q0)     s[nb][0] = -1e30f;
                if (k0 + 1 > q0) s[nb][1] = -1e30f;
                if (k0 > q1)     s[nb][2] = -1e30f;
                if (k0 + 1 > q1) s[nb][3] = -1e30f;
            }
        }

        // Online softmax: rows g (c0,c1) and g+8 (c2,c3); reduce over 4 lanes
        float mx0 = -1e30f, mx1 = -1e30f;
#pragma unroll
        for (int nb = 0; nb < 8; nb++) {
            mx0 = fmaxf(mx0, fmaxf(s[nb][0], s[nb][1]));
            mx1 = fmaxf(mx1, fmaxf(s[nb][2], s[nb][3]));
        }
#pragma unroll
        for (int off = 1; off < 4; off <<= 1) {
            mx0 = fmaxf(mx0, __shfl_xor_sync(0xffffffffu, mx0, off));
            mx1 = fmaxf(mx1, __shfl_xor_sync(0xffffffffu, mx1, off));
        }
        float mn0 = fmaxf(m0, mx0), mn1 = fmaxf(m1, mx1);
        float f0 = __expf(m0 - mn0), f1 = __expf(m1 - mn1);
        m0 = mn0; m1 = mn1;

        float rs0 = 0.0f, rs1 = 0.0f;
#pragma unroll
        for (int nb = 0; nb < 8; nb++) {
            s[nb][0] = __expf(s[nb][0] - mn0);
            s[nb][1] = __expf(s[nb][1] - mn0);
            s[nb][2] = __expf(s[nb][2] - mn1);
            s[nb][3] = __expf(s[nb][3] - mn1);
            rs0 += s[nb][0] + s[nb][1];
            rs1 += s[nb][2] + s[nb][3];
        }
#pragma unroll
        for (int off = 1; off < 4; off <<= 1) {
            rs0 += __shfl_xor_sync(0xffffffffu, rs0, off);
            rs1 += __shfl_xor_sync(0xffffffffu, rs1, off);
        }
        l0s = l0s * f0 + rs0;
        l1s = l1s * f1 + rs1;
#pragma unroll
        for (int nb = 0; nb < 8; nb++) {
            o[nb][0] *= f0; o[nb][1] *= f0;
            o[nb][2] *= f1; o[nb][3] *= f1;
        }

        // O += P V : P packed in-register (QK C-frag == PV A-frag layout)
#pragma unroll
        for (int ks = 0; ks < 4; ks++) {
            uint32_t pah[4], pal[4];
            cvt2(s[2 * ks][0],     s[2 * ks][1],     pah[0], pal[0]);
            cvt2(s[2 * ks][2],     s[2 * ks][3],     pah[1], pal[1]);
            cvt2(s[2 * ks + 1][0], s[2 * ks + 1][1], pah[2], pal[2]);
            cvt2(s[2 * ks + 1][2], s[2 * ks + 1][3], pah[3], pal[3]);
#pragma unroll
            for (int nb = 0; nb < 8; nb++) {
                uint32_t vh2[2], vl2[2];
                int vbase = (ks * 8 + tig) * AK_STRIDE + nb * 8 + g;
                vh2[0] = Vh[vbase];
                vh2[1] = Vh[vbase + 4 * AK_STRIDE];
                vl2[0] = Vl[vbase];
                vl2[1] = Vl[vbase + 4 * AK_STRIDE];
                MMA_BF16(o[nb], pah, vh2);
                MMA_BF16(o[nb], pah, vl2);
                MMA_BF16(o[nb], pal, vh2);
            }
        }
    }

    // Epilogue: normalize, write g_ao[b*S+q][h*64+d]
    const int b = bh >> 4, h = bh & 15;
    const float inv0 = 1.0f / l0s, inv1 = 1.0f / l1s;
    int q0 = qb * 128 + wid * 16 + g;
#pragma unroll
    for (int nb = 0; nb < 8; nb++) {
        int d = nb * 8 + tig * 2;
        float2 v0 = make_float2(o[nb][0] * inv0, o[nb][1] * inv0);
        *(float2*)(g_ao + ((size_t)(b * S_LEN + q0)) * HID + h * HD + d) = v0;
        float2 v1 = make_float2(o[nb][2] * inv1, o[nb][3] * inv1);
        *(float2*)(g_ao + ((size_t)(b * S_LEN + q0 + 8)) * HID + h * HD + d) = v1;
    }
}

// ---------------------------------------------------------------------------
extern "C" void kernel_launch(void* const* d_in, const int* in_sizes, int n_in,
                              void* d_out, int out_size)
{
    const float* x     = (const float*)d_in[0];
    const float* w_qkv = (const float*)d_in[1];
    const float* w_o   = (const float*)d_in[2];
    float* out = (float*)d_out;

    cudaFuncSetAttribute(attn_mma_kernel,
                         cudaFuncAttributeMaxDynamicSharedMemorySize, ATTN_MMA_SMEM);
    cudaFuncSetAttribute(gemm_mma_kernel<0>,
                         cudaFuncAttributeMaxDynamicSharedMemorySize, GEMM_SMEM);
    cudaFuncSetAttribute(gemm_mma_kernel<1>,
                         cudaFuncAttributeMaxDynamicSharedMemorySize, GEMM_SMEM);

    // 0) RoPE cos/sin tables (double-precision trig, fast-math-proof)
    rope_table_kernel<<<(S_LEN * 32) / 256, 256>>>();

    // 1) QKV projection (HMMA bf16 hi/lo, double-buffered) -> q/k/v head-major
    gemm_mma_kernel<0><<<dim3(3 * HID / 128, M_TOT / 128), 256, GEMM_SMEM>>>(
        x, w_qkv, nullptr, 3 * HID, HID);

    // 2) RoPE on q and k in place
    rope_kernel<<<(2 * BH * S_LEN * 32) / 256, 256>>>();

    // 3) Causal flash attention (HMMA bf16 hi/lo, BQ=128, P in registers)
    attn_mma_kernel<<<dim3(S_LEN / 128, BH), 256, ATTN_MMA_SMEM>>>();

    // 4) Output projection (HMMA bf16 hi/lo, double-buffered) -> d_out
    gemm_mma_kernel<1><<<dim3(HID / 128, M_TOT / 128), 256, GEMM_SMEM>>>(
        nullptr, w_o, out, HID, HID);
}